// round 2
// baseline (speedup 1.0000x reference)
#include <cuda_runtime.h>

// Sliding-window attention, B=2 H=16 S=4096 D=64 W=256, non-causal, fp32.
// Effective mask: |ki - qi| <= 256 and 0 <= ki < S  (band subsumed by the
// reference's 3-block neighbor gather).
//
// Design: 1 thread = 1 query row. Online softmax fully in registers.
// f32x2 packed FMA (Blackwell) for QK and PV. Double-buffered smem K/V tiles.

#define SQ   4096
#define HD   64
#define WIN  256
#define QT   128     // queries per CTA (= threads)
#define KT   32      // keys per tile
#define BH   32      // batch*heads

typedef unsigned long long ull;

__device__ __forceinline__ ull ffma2(ull a, ull b, ull c) {
    ull d;
    asm("fma.rn.f32x2 %0, %1, %2, %3;" : "=l"(d) : "l"(a), "l"(b), "l"(c));
    return d;
}
__device__ __forceinline__ ull fadd2(ull a, ull b) {
    ull d;
    asm("add.rn.f32x2 %0, %1, %2;" : "=l"(d) : "l"(a), "l"(b));
    return d;
}
__device__ __forceinline__ ull fmul2(ull a, ull b) {
    ull d;
    asm("mul.rn.f32x2 %0, %1, %2;" : "=l"(d) : "l"(a), "l"(b));
    return d;
}
__device__ __forceinline__ ull pack2(float lo, float hi) {
    ull r;
    asm("mov.b64 %0, {%1, %2};" : "=l"(r) : "f"(lo), "f"(hi));
    return r;
}
__device__ __forceinline__ ull splat2(float x) {
    ull r;
    asm("mov.b64 %0, {%1, %1};" : "=l"(r) : "f"(x));
    return r;
}
__device__ __forceinline__ void unpack2(ull v, float& lo, float& hi) {
    asm("mov.b64 {%0, %1}, %2;" : "=f"(lo), "=f"(hi) : "l"(v));
}
__device__ __forceinline__ float ex2(float x) {
    float y;
    asm("ex2.approx.f32 %0, %1;" : "=f"(y) : "f"(x));
    return y;
}

__global__ __launch_bounds__(128, 2)
void swa_kernel(const float* __restrict__ Qg, const float* __restrict__ Kg,
                const float* __restrict__ Vg, float* __restrict__ Og)
{
    __shared__ __align__(16) float Ks[2][KT * HD];
    __shared__ __align__(16) float Vs[2][KT * HD];

    const int tid = threadIdx.x;
    const int q0  = blockIdx.x * QT;
    const int bh  = blockIdx.y;
    const int qi  = q0 + tid;
    const size_t base = (size_t)bh * SQ * HD;

    const float SCALE = 0.125f;                    // 1/sqrt(64)
    const float L2E   = 1.4426950408889634f;
    const float MASKV = -1.0e30f;

    // Q row -> 32 packed f32x2 registers, prescaled by 1/sqrt(D)
    ull Qr[32];
    {
        const float4* qp = (const float4*)(Qg + base + (size_t)qi * HD);
#pragma unroll
        for (int i = 0; i < 16; i++) {
            float4 t = qp[i];
            Qr[2 * i]     = pack2(t.x * SCALE, t.y * SCALE);
            Qr[2 * i + 1] = pack2(t.z * SCALE, t.w * SCALE);
        }
    }

    const int lo = max(qi - WIN, 0);        // inclusive band
    const int hi = min(qi + WIN, SQ - 1);
    const int kfirst = max(q0 - WIN, 0);                 // 32-aligned by construction
    const int klast  = min(q0 + QT - 1 + WIN, SQ - 1);
    const int qw0 = q0 + (tid & ~31);                    // warp's first query

    const float4* K4 = (const float4*)(Kg + base);
    const float4* V4 = (const float4*)(Vg + base);
    const int rbase = tid >> 4;   // 0..7
    const int cc    = tid & 15;   // 0..15  (float4 column within 64-float row)

    // Prime buffer 0 with the first tile.
    {
        float4* Kd = (float4*)Ks[0];
        float4* Vd = (float4*)Vs[0];
#pragma unroll
        for (int j = 0; j < 4; j++) {
            int r  = j * 8 + rbase;
            int kg = kfirst + r;
            float4 kv = make_float4(0.f, 0.f, 0.f, 0.f);
            float4 vv = make_float4(0.f, 0.f, 0.f, 0.f);
            if (kg < SQ) { kv = K4[kg * 16 + cc]; vv = V4[kg * 16 + cc]; }
            Kd[r * 16 + cc] = kv;
            Vd[r * 16 + cc] = vv;
        }
    }
    __syncthreads();

    float m = -5.0e29f;   // strictly > MASKV so all-masked tiles exp to 0
    float l = 0.f;
    ull O2[32];
#pragma unroll
    for (int i = 0; i < 32; i++) O2[i] = 0ULL;

    int buf = 0;
    for (int kb = kfirst; kb <= klast; kb += KT) {
        // ---- prefetch next tile into registers (hides DRAM latency) ----
        const int  kbn      = kb + KT;
        const bool has_next = (kbn <= klast);
        float4 kst[4], vst[4];
        if (has_next) {
#pragma unroll
            for (int j = 0; j < 4; j++) {
                int r  = j * 8 + rbase;
                int kg = kbn + r;
                if (kg < SQ) { kst[j] = K4[kg * 16 + cc]; vst[j] = V4[kg * 16 + cc]; }
                else {
                    kst[j] = make_float4(0.f, 0.f, 0.f, 0.f);
                    vst[j] = make_float4(0.f, 0.f, 0.f, 0.f);
                }
            }
        }

        // ---- compute on current tile (skip if warp band misses the tile) ----
        const bool wact = (kb + KT - 1 >= qw0 - WIN) && (kb <= qw0 + 31 + WIN);
        if (wact) {
            // QK^T for this thread's query row vs 32 keys
            float s[KT];
            const float* Kt = Ks[buf];
#pragma unroll
            for (int k = 0; k < KT; k++) {
                const ulonglong2* kp = (const ulonglong2*)(Kt + k * HD);
                ull a0 = 0ULL, a1 = 0ULL;
#pragma unroll
                for (int i = 0; i < 16; i++) {
                    ulonglong2 kv = kp[i];                 // LDS.128, warp-uniform
                    a0 = ffma2(Qr[2 * i],     kv.x, a0);
                    a1 = ffma2(Qr[2 * i + 1], kv.y, a1);
                }
                ull aa = fadd2(a0, a1);
                float x, y;
                unpack2(aa, x, y);
                s[k] = x + y;
            }

            // band mask (assignment kills any garbage from padded rows)
            const int kl = lo - kb, kh = hi - kb;
#pragma unroll
            for (int k = 0; k < KT; k++)
                if (k < kl || k > kh) s[k] = MASKV;

            // tile max (4-way partial trees)
            float m0 = s[0], m1 = s[1], m2 = s[2], m3 = s[3];
#pragma unroll
            for (int k = 4; k < KT; k += 4) {
                m0 = fmaxf(m0, s[k]);     m1 = fmaxf(m1, s[k + 1]);
                m2 = fmaxf(m2, s[k + 2]); m3 = fmaxf(m3, s[k + 3]);
            }
            const float mt   = fmaxf(fmaxf(m0, m1), fmaxf(m2, m3));
            const float mnew = fmaxf(m, mt);
            const float alpha = ex2((m - mnew) * L2E);
            m = mnew;

            float p0 = 0.f, p1 = 0.f, p2 = 0.f, p3 = 0.f;
#pragma unroll
            for (int k = 0; k < KT; k += 4) {
                s[k]     = ex2((s[k]     - mnew) * L2E); p0 += s[k];
                s[k + 1] = ex2((s[k + 1] - mnew) * L2E); p1 += s[k + 1];
                s[k + 2] = ex2((s[k + 2] - mnew) * L2E); p2 += s[k + 2];
                s[k + 3] = ex2((s[k + 3] - mnew) * L2E); p3 += s[k + 3];
            }
            l = l * alpha + ((p0 + p1) + (p2 + p3));

            const ull al2 = splat2(alpha);
#pragma unroll
            for (int i = 0; i < 32; i++) O2[i] = fmul2(O2[i], al2);

            // P·V accumulate
            const float* Vt = Vs[buf];
#pragma unroll
            for (int k = 0; k < KT; k++) {
                const ull pk = splat2(s[k]);
                const ulonglong2* vp = (const ulonglong2*)(Vt + k * HD);
#pragma unroll
                for (int i = 0; i < 16; i++) {
                    ulonglong2 vv = vp[i];                 // LDS.128, warp-uniform
                    O2[2 * i]     = ffma2(pk, vv.x, O2[2 * i]);
                    O2[2 * i + 1] = ffma2(pk, vv.y, O2[2 * i + 1]);
                }
            }
        }

        // ---- commit prefetched tile to the other buffer ----
        if (has_next) {
            float4* Kd = (float4*)Ks[buf ^ 1];
            float4* Vd = (float4*)Vs[buf ^ 1];
#pragma unroll
            for (int j = 0; j < 4; j++) {
                int r = j * 8 + rbase;
                Kd[r * 16 + cc] = kst[j];
                Vd[r * 16 + cc] = vst[j];
            }
        }
        __syncthreads();
        buf ^= 1;
    }

    // epilogue: normalize and store (every q has >= 257 valid keys, l > 0)
    const float inv  = 1.0f / l;
    const ull   inv2 = splat2(inv);
    float4* op = (float4*)(Og + base + (size_t)qi * HD);
#pragma unroll
    for (int i = 0; i < 16; i++) {
        ull o0 = fmul2(O2[2 * i],     inv2);
        ull o1 = fmul2(O2[2 * i + 1], inv2);
        float4 o;
        unpack2(o0, o.x, o.y);
        unpack2(o1, o.z, o.w);
        op[i] = o;
    }
}

extern "C" void kernel_launch(void* const* d_in, const int* in_sizes, int n_in,
                              void* d_out, int out_size)
{
    const float* Q = (const float*)d_in[0];
    const float* K = (const float*)d_in[1];
    const float* V = (const float*)d_in[2];
    float* O = (float*)d_out;
    (void)in_sizes; (void)n_in; (void)out_size;

    dim3 grid(SQ / QT, BH);   // (32, 32) = 1024 CTAs
    swa_kernel<<<grid, 128>>>(Q, K, V, O);
}